// round 5
// baseline (speedup 1.0000x reference)
#include <cuda_runtime.h>
#include <stdint.h>

#define B 64
#define H 1024
#define S 4096
#define NOPS 8
#define TSTEPS 10

typedef unsigned long long ull;

// ---- kernel A (x-logits): tile 64b x 128s, K-split 16 ----
#define K1_SB 128
#define K1_NSB (S / K1_SB)           // 32
#define K1_KSPLIT 16
#define K1_KR (H / K1_KSPLIT)        // 64
#define K1_KC 16
#define K1_NC (K1_KR / K1_KC)        // 4
#define K1_GEMM (K1_NSB * K1_KSPLIT) // 512
#define K1_NOPB 16
#define KA_GRID (K1_GEMM + K1_NOPB)

// ---- kernel B (update): tile 64b x 64j, K-split 32 ----
#define K2_JB 64
#define K2_NJB (H / K2_JB)           // 16
#define K2_KSPLIT 32
#define K2_K (2 * H)
#define K2_KR (K2_K / K2_KSPLIT)     // 64
#define K2_KC 16
#define K2_NC (K2_KR / K2_KC)        // 4
#define K2_GEMM (K2_NJB * K2_KSPLIT) // 512
#define NAMB 512                     // argmax partial blocks (B x 8 segments)
#define KB_GRID (NAMB + K2_GEMM)     // 1024

// ---- persistent scratch ----
__device__ float g_hn[B * H];
__device__ float g_px[K1_KSPLIT][B][S];   // 16 MB
__device__ float g_pu[K2_KSPLIT][B][H];   // 8 MB
__device__ ull   g_amax[B];
__device__ int   g_opflag[TSTEPS][B];
__device__ int   g_done_flag[TSTEPS];
__device__ int   g_arrived;

__device__ __forceinline__ ull ffma2(ull a, ull b, ull c) {
    ull d;
    asm("fma.rn.f32x2 %0, %1, %2, %3;" : "=l"(d) : "l"(a), "l"(b), "l"(c));
    return d;
}
__device__ __forceinline__ unsigned f2ord(float f) {
    unsigned u = __float_as_uint(f);
    return (u & 0x80000000u) ? ~u : (u | 0x80000000u);
}

// ============ KF: combine pu -> h, produce h_n(t), reset step state =========
// grid = 2*B + 1 blocks of 128 threads. Blocks 0..127 combine (512 j each);
// block 128 computes done flag + resets step state.
__global__ __launch_bounds__(128) void kf(
    int t, const float* __restrict__ bres, const float* __restrict__ noise)
{
    const int tid = threadIdx.x;

    if (blockIdx.x == 2 * B) {
        int dn = 0;
        for (int tp = 0; tp < t; tp++) {
            int f = (tid < B) ? g_opflag[tp][tid] : 1;
            dn |= __syncthreads_and(f);
        }
        if (tid == 0) { g_done_flag[t] = dn; g_arrived = 0; }
        if (tid < B) g_amax[tid] = 0ull;
        return;
    }

    const int b = blockIdx.x >> 1;
    const int j = (blockIdx.x & 1) * 512 + tid * 4;

    float4 h4 = make_float4(0.f, 0.f, 0.f, 0.f);
    if (t > 0) {
#pragma unroll
        for (int ks = 0; ks < K2_KSPLIT; ks++) {
            float4 p = *(const float4*)&g_pu[ks][b][j];
            h4.x += p.x; h4.y += p.y; h4.z += p.z; h4.w += p.w;
        }
        float4 bb = *(const float4*)&bres[j];
        h4.x += bb.x; h4.y += bb.y; h4.z += bb.z; h4.w += bb.w;
    }
    float4 nz = *(const float4*)&noise[((size_t)t * B + b) * H + j];
    float4 hn = make_float4(h4.x + 0.01f * nz.x, h4.y + 0.01f * nz.y,
                            h4.z + 0.01f * nz.z, h4.w + 0.01f * nz.w);
    *(float4*)&g_hn[b * H + j] = hn;
}

// ============ KA: x-logit partial GEMM + op-logits ==========================
__global__ __launch_bounds__(256) void ka(
    int t, const float* __restrict__ Wx,
    const float* __restrict__ Wop, const float* __restrict__ bop)
{
    const int tid = threadIdx.x;
    const float* __restrict__ hn = g_hn;

    if (blockIdx.x >= K1_GEMM) {
        // ------- op-logits block: 4 batch rows, full K -------
        __shared__ float sOp[4][64][NOPS];
        __shared__ float sSum[4][NOPS];
        const int b0 = (blockIdx.x - K1_GEMM) * 4;
        const int lb = tid >> 6, seg = tid & 63;
        const int b = b0 + lb, kb = seg * 16;
        float part[NOPS];
#pragma unroll
        for (int o = 0; o < NOPS; o++) part[o] = 0.f;
        const float4* wp = (const float4*)(Wop + (size_t)kb * NOPS);
#pragma unroll
        for (int g = 0; g < 4; g++) {
            float4 a4 = *(const float4*)&hn[b * H + kb + g * 4];
            float av[4] = {a4.x, a4.y, a4.z, a4.w};
#pragma unroll
            for (int c = 0; c < 4; c++) {
                float4 w0 = wp[(g * 4 + c) * 2], w1 = wp[(g * 4 + c) * 2 + 1];
                float a = av[c];
                part[0] += a * w0.x; part[1] += a * w0.y;
                part[2] += a * w0.z; part[3] += a * w0.w;
                part[4] += a * w1.x; part[5] += a * w1.y;
                part[6] += a * w1.z; part[7] += a * w1.w;
            }
        }
#pragma unroll
        for (int o = 0; o < NOPS; o++) sOp[lb][seg][o] = part[o];
        __syncthreads();
        if (tid < 32) {
            int rb = tid >> 3, o = tid & 7;
            float s = 0.f;
            for (int g = 0; g < 64; g++) s += sOp[rb][g][o];
            sSum[rb][o] = s;
        }
        __syncthreads();
        if (tid < 4) {
            float best = __int_as_float(0xff800000); int bi = -1;
#pragma unroll
            for (int o = 0; o < NOPS; o++) {
                float v = sSum[tid][o] + bop[o];
                if (v > best) { best = v; bi = o; }
            }
            g_opflag[t][b0 + tid] = (bi == 0) ? 1 : 0;
        }
        return;
    }

    // ------- GEMM block -------
    __shared__ __align__(16) float2 sA[2][K1_KC][B];       // (h,h) dup pairs
    __shared__ __align__(16) float  sB[2][K1_KC][K1_SB];   // raw weights

    const int ks = blockIdx.x >> 5, sb = blockIdx.x & 31;
    const int s0 = sb * K1_SB, k0 = ks * K1_KR;
    const int sx = tid & 15, byy = tid >> 4;
    const int fb = tid >> 2, fg = tid & 3;     // A fill
    const int wk = tid >> 4, wg = tid & 15;    // B fill

    ull acc[4][4];
#pragma unroll
    for (int p = 0; p < 4; p++)
#pragma unroll
        for (int q = 0; q < 4; q++) acc[p][q] = 0ull;

    {   // fill chunk 0
        float4 a = *(const float4*)&hn[fb * H + k0 + fg * 4];
        sA[0][fg * 4 + 0][fb] = make_float2(a.x, a.x);
        sA[0][fg * 4 + 1][fb] = make_float2(a.y, a.y);
        sA[0][fg * 4 + 2][fb] = make_float2(a.z, a.z);
        sA[0][fg * 4 + 3][fb] = make_float2(a.w, a.w);
        const float* wr = Wx + (size_t)(k0 + wk) * S + s0 + wg * 8;
        *(float4*)&sB[0][wk][wg * 8]     = *(const float4*)wr;
        *(float4*)&sB[0][wk][wg * 8 + 4] = *(const float4*)(wr + 4);
    }
    __syncthreads();

    for (int c = 0; c < K1_NC; c++) {
        const int cur = c & 1;
        float4 pa, pw0, pw1;
        if (c + 1 < K1_NC) {
            const int kb = k0 + (c + 1) * K1_KC;
            pa = *(const float4*)&hn[fb * H + kb + fg * 4];
            const float* wr = Wx + (size_t)(kb + wk) * S + s0 + wg * 8;
            pw0 = *(const float4*)wr;
            pw1 = *(const float4*)(wr + 4);
        }
#pragma unroll
        for (int kk = 0; kk < K1_KC; kk++) {
            ulonglong2 a01 = *(const ulonglong2*)&sA[cur][kk][byy * 4];
            ulonglong2 a23 = *(const ulonglong2*)&sA[cur][kk][byy * 4 + 2];
            ulonglong2 w01 = *(const ulonglong2*)&sB[cur][kk][sx * 4];
            ulonglong2 w23 = *(const ulonglong2*)&sB[cur][kk][64 + sx * 4];
            acc[0][0] = ffma2(a01.x, w01.x, acc[0][0]);
            acc[0][1] = ffma2(a01.x, w01.y, acc[0][1]);
            acc[0][2] = ffma2(a01.x, w23.x, acc[0][2]);
            acc[0][3] = ffma2(a01.x, w23.y, acc[0][3]);
            acc[1][0] = ffma2(a01.y, w01.x, acc[1][0]);
            acc[1][1] = ffma2(a01.y, w01.y, acc[1][1]);
            acc[1][2] = ffma2(a01.y, w23.x, acc[1][2]);
            acc[1][3] = ffma2(a01.y, w23.y, acc[1][3]);
            acc[2][0] = ffma2(a23.x, w01.x, acc[2][0]);
            acc[2][1] = ffma2(a23.x, w01.y, acc[2][1]);
            acc[2][2] = ffma2(a23.x, w23.x, acc[2][2]);
            acc[2][3] = ffma2(a23.x, w23.y, acc[2][3]);
            acc[3][0] = ffma2(a23.y, w01.x, acc[3][0]);
            acc[3][1] = ffma2(a23.y, w01.y, acc[3][1]);
            acc[3][2] = ffma2(a23.y, w23.x, acc[3][2]);
            acc[3][3] = ffma2(a23.y, w23.y, acc[3][3]);
        }
        if (c + 1 < K1_NC) {
            const int nxt = (c + 1) & 1;
            sA[nxt][fg * 4 + 0][fb] = make_float2(pa.x, pa.x);
            sA[nxt][fg * 4 + 1][fb] = make_float2(pa.y, pa.y);
            sA[nxt][fg * 4 + 2][fb] = make_float2(pa.z, pa.z);
            sA[nxt][fg * 4 + 3][fb] = make_float2(pa.w, pa.w);
            *(float4*)&sB[nxt][wk][wg * 8]     = pw0;
            *(float4*)&sB[nxt][wk][wg * 8 + 4] = pw1;
            __syncthreads();
        }
    }

#pragma unroll
    for (int p = 0; p < 4; p++) {
        const int b = byy * 4 + p;
        *(ulonglong2*)&g_px[ks][b][s0 + sx * 4]      = make_ulonglong2(acc[p][0], acc[p][1]);
        *(ulonglong2*)&g_px[ks][b][s0 + 64 + sx * 4] = make_ulonglong2(acc[p][2], acc[p][3]);
    }
}

// ============ KB: argmax partial blocks + update GEMM (spin for gather) =====
__global__ __launch_bounds__(128) void kb(
    int t, const float* __restrict__ s2a, const float* __restrict__ Wres,
    const float* __restrict__ bx)
{
    const int tid = threadIdx.x;

    if (blockIdx.x < NAMB) {
        // ------- argmax partial block: one (b, 512-wide s segment) -------
        __shared__ ull red[4];
        const int b = blockIdx.x >> 3;
        const int s = (blockIdx.x & 7) * 512 + tid * 4;
        float4 v = *(const float4*)&bx[s];
#pragma unroll
        for (int ks = 0; ks < K1_KSPLIT; ks++) {
            float4 p = *(const float4*)&g_px[ks][b][s];
            v.x += p.x; v.y += p.y; v.z += p.z; v.w += p.w;
        }
        float best = v.x; int bi = s;
        if (v.y > best) { best = v.y; bi = s + 1; }
        if (v.z > best) { best = v.z; bi = s + 2; }
        if (v.w > best) { best = v.w; bi = s + 3; }
        ull key = ((ull)f2ord(best) << 32) | (ull)(0xFFFFFFFFu - (unsigned)bi);
#pragma unroll
        for (int off = 16; off; off >>= 1) {
            ull o = __shfl_down_sync(0xFFFFFFFFu, key, off);
            if (o > key) key = o;
        }
        if ((tid & 31) == 0) red[tid >> 5] = key;
        __syncthreads();
        if (tid == 0) {
            ull k = red[0];
#pragma unroll
            for (int w = 1; w < 4; w++) if (red[w] > k) k = red[w];
            atomicMax(&g_amax[b], k);   // max: order-independent, deterministic
            __threadfence();
            atomicAdd(&g_arrived, 1);
        }
        return;
    }

    // ------- GEMM block -------
    if (g_done_flag[t]) return;   // frozen: keep pu (h stays fixed)

    __shared__ __align__(16) float2 sA[2][K2_KC][B];
    __shared__ __align__(16) float  sB[2][K2_KC][K2_JB];
    __shared__ int sPtr[B];

    const int q = blockIdx.x - NAMB;
    const int ks = q >> 4, jb = q & 15;
    const int k0 = ks * K2_KR, j0 = jb * K2_JB;
    const bool gat = (k0 >= H);
    const float* __restrict__ hn = g_hn;

    if (gat) {
        if (tid == 0) {
            while (atomicAdd(&g_arrived, 0) < NAMB) __nanosleep(128);
        }
        __syncthreads();
        __threadfence();
        if (tid < B) {
            ull k = g_amax[tid];
            int p = (int)(0xFFFFFFFFu - (unsigned)(k & 0xFFFFFFFFull));
            sPtr[tid] = (p < S) ? p : (S - 1);
        }
        __syncthreads();
    }

    const int fb = tid >> 1, fg = tid & 1;   // A fill
    const int wk = tid >> 3, wg = tid & 7;   // B fill
    const int byy = tid >> 3, jx = tid & 7;

    ull acc[4][4];
#pragma unroll
    for (int p = 0; p < 4; p++)
#pragma unroll
        for (int q2 = 0; q2 < 4; q2++) acc[p][q2] = 0ull;

    const float* arow0 = gat ? s2a + ((size_t)fb * S + sPtr[fb]) * H + (k0 - H)
                             : hn + fb * H + k0;

    {   // fill chunk 0
        float4 a0 = *(const float4*)(arow0 + fg * 8);
        float4 a1 = *(const float4*)(arow0 + fg * 8 + 4);
        sA[0][fg * 8 + 0][fb] = make_float2(a0.x, a0.x);
        sA[0][fg * 8 + 1][fb] = make_float2(a0.y, a0.y);
        sA[0][fg * 8 + 2][fb] = make_float2(a0.z, a0.z);
        sA[0][fg * 8 + 3][fb] = make_float2(a0.w, a0.w);
        sA[0][fg * 8 + 4][fb] = make_float2(a1.x, a1.x);
        sA[0][fg * 8 + 5][fb] = make_float2(a1.y, a1.y);
        sA[0][fg * 8 + 6][fb] = make_float2(a1.z, a1.z);
        sA[0][fg * 8 + 7][fb] = make_float2(a1.w, a1.w);
        const float* wr = Wres + (size_t)(k0 + wk) * H + j0 + wg * 8;
        *(float4*)&sB[0][wk][wg * 8]     = *(const float4*)wr;
        *(float4*)&sB[0][wk][wg * 8 + 4] = *(const float4*)(wr + 4);
    }
    __syncthreads();

    for (int c = 0; c < K2_NC; c++) {
        const int cur = c & 1;
        float4 pa0, pa1, pw0, pw1;
        if (c + 1 < K2_NC) {
            const int kof = (c + 1) * K2_KC;
            pa0 = *(const float4*)(arow0 + kof + fg * 8);
            pa1 = *(const float4*)(arow0 + kof + fg * 8 + 4);
            const float* wr = Wres + (size_t)(k0 + kof + wk) * H + j0 + wg * 8;
            pw0 = *(const float4*)wr;
            pw1 = *(const float4*)(wr + 4);
        }
#pragma unroll
        for (int kk = 0; kk < K2_KC; kk++) {
            ulonglong2 a01 = *(const ulonglong2*)&sA[cur][kk][byy * 4];
            ulonglong2 a23 = *(const ulonglong2*)&sA[cur][kk][byy * 4 + 2];
            ulonglong2 w01 = *(const ulonglong2*)&sB[cur][kk][jx * 4];
            ulonglong2 w23 = *(const ulonglong2*)&sB[cur][kk][32 + jx * 4];
            acc[0][0] = ffma2(a01.x, w01.x, acc[0][0]);
            acc[0][1] = ffma2(a01.x, w01.y, acc[0][1]);
            acc[0][2] = ffma2(a01.x, w23.x, acc[0][2]);
            acc[0][3] = ffma2(a01.x, w23.y, acc[0][3]);
            acc[1][0] = ffma2(a01.y, w01.x, acc[1][0]);
            acc[1][1] = ffma2(a01.y, w01.y, acc[1][1]);
            acc[1][2] = ffma2(a01.y, w23.x, acc[1][2]);
            acc[1][3] = ffma2(a01.y, w23.y, acc[1][3]);
            acc[2][0] = ffma2(a23.x, w01.x, acc[2][0]);
            acc[2][1] = ffma2(a23.x, w01.y, acc[2][1]);
            acc[2][2] = ffma2(a23.x, w23.x, acc[2][2]);
            acc[2][3] = ffma2(a23.x, w23.y, acc[2][3]);
            acc[3][0] = ffma2(a23.y, w01.x, acc[3][0]);
            acc[3][1] = ffma2(a23.y, w01.y, acc[3][1]);
            acc[3][2] = ffma2(a23.y, w23.x, acc[3][2]);
            acc[3][3] = ffma2(a23.y, w23.y, acc[3][3]);
        }
        if (c + 1 < K2_NC) {
            const int nxt = (c + 1) & 1;
            sA[nxt][fg * 8 + 0][fb] = make_float2(pa0.x, pa0.x);
            sA[nxt][fg * 8 + 1][fb] = make_float2(pa0.y, pa0.y);
            sA[nxt][fg * 8 + 2][fb] = make_float2(pa0.z, pa0.z);
            sA[nxt][fg * 8 + 3][fb] = make_float2(pa0.w, pa0.w);
            sA[nxt][fg * 8 + 4][fb] = make_float2(pa1.x, pa1.x);
            sA[nxt][fg * 8 + 5][fb] = make_float2(pa1.y, pa1.y);
            sA[nxt][fg * 8 + 6][fb] = make_float2(pa1.z, pa1.z);
            sA[nxt][fg * 8 + 7][fb] = make_float2(pa1.w, pa1.w);
            *(float4*)&sB[nxt][wk][wg * 8]     = pw0;
            *(float4*)&sB[nxt][wk][wg * 8 + 4] = pw1;
            __syncthreads();
        }
    }

#pragma unroll
    for (int p = 0; p < 4; p++) {
        const int b = byy * 4 + p;
        *(ulonglong2*)&g_pu[ks][b][j0 + jx * 4]      = make_ulonglong2(acc[p][0], acc[p][1]);
        *(ulonglong2*)&g_pu[ks][b][j0 + 32 + jx * 4] = make_ulonglong2(acc[p][2], acc[p][3]);
    }
}

// ============ KO: final combine -> out =====================================
__global__ __launch_bounds__(256) void ko(const float* __restrict__ bres,
                                          float* __restrict__ out)
{
    const int b = blockIdx.x, tid = threadIdx.x;
    const int j = tid * 4;
    float4 a = make_float4(0.f, 0.f, 0.f, 0.f);
#pragma unroll
    for (int ks = 0; ks < K2_KSPLIT; ks++) {
        float4 p = *(const float4*)&g_pu[ks][b][j];
        a.x += p.x; a.y += p.y; a.z += p.z; a.w += p.w;
    }
    float4 bb = *(const float4*)&bres[j];
    *(float4*)&out[b * H + j] = make_float4(a.x + bb.x, a.y + bb.y,
                                            a.z + bb.z, a.w + bb.w);
}

extern "C" void kernel_launch(void* const* d_in, const int* in_sizes, int n_in,
                              void* d_out, int out_size) {
    const float* s2a   = (const float*)d_in[0];
    const float* Wres  = (const float*)d_in[1];
    const float* bres  = (const float*)d_in[2];
    const float* Wop   = (const float*)d_in[3];
    const float* bop   = (const float*)d_in[4];
    const float* Wx    = (const float*)d_in[5];
    const float* bx    = (const float*)d_in[6];
    const float* noise = (const float*)d_in[7];
    float* out = (float*)d_out;

    for (int t = 0; t < TSTEPS; t++) {
        kf<<<2 * B + 1, 128>>>(t, bres, noise);
        ka<<<KA_GRID, 256>>>(t, Wx, Wop, bop);
        kb<<<KB_GRID, 128>>>(t, s2a, Wres, bx);
    }
    ko<<<B, 256>>>(bres, out);
}

// round 6
// speedup vs baseline: 1.0890x; 1.0890x over previous
#include <cuda_runtime.h>
#include <stdint.h>

#define B 64
#define H 1024
#define S 4096
#define NOPS 8
#define TSTEPS 10

typedef unsigned long long ull;

// ---- kernel A (x-logits): tile 64b x 128s, K-split 16 ----
#define K1_SB 128
#define K1_NSB (S / K1_SB)           // 32
#define K1_KSPLIT 16
#define K1_KR (H / K1_KSPLIT)        // 64
#define K1_KC 16
#define K1_NC (K1_KR / K1_KC)        // 4
#define K1_GEMM (K1_NSB * K1_KSPLIT) // 512
#define K1_NOPB 16
#define KA_GRID (K1_GEMM + K1_NOPB)

// ---- kernel B (update): tile 64b x 64j, K-split 16 ----
#define K2_JB 64
#define K2_NJB (H / K2_JB)           // 16
#define K2_KSPLIT 16
#define K2_K (2 * H)
#define K2_KR (K2_K / K2_KSPLIT)     // 128
#define K2_KC 16
#define K2_NC (K2_KR / K2_KC)        // 8
#define K2_GEMM (K2_NJB * K2_KSPLIT) // 256
#define NAMB 512                     // argmax partial blocks (B x 8 segments)
#define KB_GRID (NAMB + K2_GEMM)     // 768

// ---- persistent scratch ----
__device__ float g_hn[B * H];
__device__ float g_px[K1_KSPLIT][B][S];   // 16 MB
__device__ float g_pu[K2_KSPLIT][B][H];   // 4 MB
__device__ ull   g_amax[B];
__device__ int   g_opflag[TSTEPS][B];
__device__ int   g_done_flag[TSTEPS];
__device__ int   g_arrived;

__device__ __forceinline__ ull ffma2(ull a, ull b, ull c) {
    ull d;
    asm("fma.rn.f32x2 %0, %1, %2, %3;" : "=l"(d) : "l"(a), "l"(b), "l"(c));
    return d;
}
__device__ __forceinline__ unsigned f2ord(float f) {
    unsigned u = __float_as_uint(f);
    return (u & 0x80000000u) ? ~u : (u | 0x80000000u);
}

// ============ KF: combine pu -> h, produce h_n(t), reset step state =========
// grid = B*8 + 1 blocks of 128 threads. Block (b, seg) combines 128 j-cols,
// threads split 32 j-quads x 4 ks-quarters. Last block: flags/reset.
__global__ __launch_bounds__(128) void kf(
    int t, const float* __restrict__ bres, const float* __restrict__ noise)
{
    const int tid = threadIdx.x;

    if (blockIdx.x == B * 8) {
        int dn = 0;
        for (int tp = 0; tp < t; tp++) {
            int f = (tid < B) ? g_opflag[tp][tid] : 1;
            dn |= __syncthreads_and(f);
        }
        if (tid == 0) { g_done_flag[t] = dn; g_arrived = 0; }
        if (tid < B) g_amax[tid] = 0ull;
        return;
    }

    __shared__ __align__(16) float4 sred[4][32];

    const int b = blockIdx.x >> 3;
    const int jseg = (blockIdx.x & 7) * 128;
    const int jq = tid & 31;     // j-quad within segment
    const int qg = tid >> 5;     // ks quarter
    const int j = jseg + jq * 4;

    float4 a = make_float4(0.f, 0.f, 0.f, 0.f);
    if (t > 0) {
#pragma unroll
        for (int ks = qg * (K2_KSPLIT / 4); ks < (qg + 1) * (K2_KSPLIT / 4); ks++) {
            float4 p = *(const float4*)&g_pu[ks][b][j];
            a.x += p.x; a.y += p.y; a.z += p.z; a.w += p.w;
        }
    }
    sred[qg][jq] = a;
    __syncthreads();
    if (qg == 0) {
        float4 a1 = sred[1][jq], a2 = sred[2][jq], a3 = sred[3][jq];
        a.x += a1.x; a.y += a1.y; a.z += a1.z; a.w += a1.w;
        a.x += a2.x; a.y += a2.y; a.z += a2.z; a.w += a2.w;
        a.x += a3.x; a.y += a3.y; a.z += a3.z; a.w += a3.w;
        if (t > 0) {
            float4 bb = *(const float4*)&bres[j];
            a.x += bb.x; a.y += bb.y; a.z += bb.z; a.w += bb.w;
        }
        float4 nz = *(const float4*)&noise[((size_t)t * B + b) * H + j];
        *(float4*)&g_hn[b * H + j] =
            make_float4(a.x + 0.01f * nz.x, a.y + 0.01f * nz.y,
                        a.z + 0.01f * nz.z, a.w + 0.01f * nz.w);
    }
}

// ============ KA: x-logit partial GEMM + op-logits ==========================
__global__ __launch_bounds__(256) void ka(
    int t, const float* __restrict__ Wx,
    const float* __restrict__ Wop, const float* __restrict__ bop)
{
    const int tid = threadIdx.x;
    const float* __restrict__ hn = g_hn;

    if (blockIdx.x >= K1_GEMM) {
        // ------- op-logits block: 4 batch rows, full K -------
        __shared__ float sOp[4][64][NOPS];
        __shared__ float sSum[4][NOPS];
        const int b0 = (blockIdx.x - K1_GEMM) * 4;
        const int lb = tid >> 6, seg = tid & 63;
        const int b = b0 + lb, kb = seg * 16;
        float part[NOPS];
#pragma unroll
        for (int o = 0; o < NOPS; o++) part[o] = 0.f;
        const float4* wp = (const float4*)(Wop + (size_t)kb * NOPS);
#pragma unroll
        for (int g = 0; g < 4; g++) {
            float4 a4 = *(const float4*)&hn[b * H + kb + g * 4];
            float av[4] = {a4.x, a4.y, a4.z, a4.w};
#pragma unroll
            for (int c = 0; c < 4; c++) {
                float4 w0 = wp[(g * 4 + c) * 2], w1 = wp[(g * 4 + c) * 2 + 1];
                float a = av[c];
                part[0] += a * w0.x; part[1] += a * w0.y;
                part[2] += a * w0.z; part[3] += a * w0.w;
                part[4] += a * w1.x; part[5] += a * w1.y;
                part[6] += a * w1.z; part[7] += a * w1.w;
            }
        }
#pragma unroll
        for (int o = 0; o < NOPS; o++) sOp[lb][seg][o] = part[o];
        __syncthreads();
        if (tid < 32) {
            int rb = tid >> 3, o = tid & 7;
            float s = 0.f;
            for (int g = 0; g < 64; g++) s += sOp[rb][g][o];
            sSum[rb][o] = s;
        }
        __syncthreads();
        if (tid < 4) {
            float best = __int_as_float(0xff800000); int bi = -1;
#pragma unroll
            for (int o = 0; o < NOPS; o++) {
                float v = sSum[tid][o] + bop[o];
                if (v > best) { best = v; bi = o; }
            }
            g_opflag[t][b0 + tid] = (bi == 0) ? 1 : 0;
        }
        return;
    }

    // ------- GEMM block -------
    __shared__ __align__(16) float2 sA[2][K1_KC][B];       // (h,h) dup pairs
    __shared__ __align__(16) float  sB[2][K1_KC][K1_SB];   // raw weights

    const int ks = blockIdx.x >> 5, sb = blockIdx.x & 31;
    const int s0 = sb * K1_SB, k0 = ks * K1_KR;
    const int sx = tid & 15, byy = tid >> 4;
    const int fb = tid >> 2, fg = tid & 3;     // A fill
    const int wk = tid >> 4, wg = tid & 15;    // B fill

    ull acc[4][4];
#pragma unroll
    for (int p = 0; p < 4; p++)
#pragma unroll
        for (int q = 0; q < 4; q++) acc[p][q] = 0ull;

    {   // fill chunk 0
        float4 a = *(const float4*)&hn[fb * H + k0 + fg * 4];
        sA[0][fg * 4 + 0][fb] = make_float2(a.x, a.x);
        sA[0][fg * 4 + 1][fb] = make_float2(a.y, a.y);
        sA[0][fg * 4 + 2][fb] = make_float2(a.z, a.z);
        sA[0][fg * 4 + 3][fb] = make_float2(a.w, a.w);
        const float* wr = Wx + (size_t)(k0 + wk) * S + s0 + wg * 8;
        *(float4*)&sB[0][wk][wg * 8]     = *(const float4*)wr;
        *(float4*)&sB[0][wk][wg * 8 + 4] = *(const float4*)(wr + 4);
    }
    __syncthreads();

    for (int c = 0; c < K1_NC; c++) {
        const int cur = c & 1;
        float4 pa, pw0, pw1;
        if (c + 1 < K1_NC) {
            const int kb = k0 + (c + 1) * K1_KC;
            pa = *(const float4*)&hn[fb * H + kb + fg * 4];
            const float* wr = Wx + (size_t)(kb + wk) * S + s0 + wg * 8;
            pw0 = *(const float4*)wr;
            pw1 = *(const float4*)(wr + 4);
        }
#pragma unroll
        for (int kk = 0; kk < K1_KC; kk++) {
            ulonglong2 a01 = *(const ulonglong2*)&sA[cur][kk][byy * 4];
            ulonglong2 a23 = *(const ulonglong2*)&sA[cur][kk][byy * 4 + 2];
            ulonglong2 w01 = *(const ulonglong2*)&sB[cur][kk][sx * 4];
            ulonglong2 w23 = *(const ulonglong2*)&sB[cur][kk][64 + sx * 4];
            acc[0][0] = ffma2(a01.x, w01.x, acc[0][0]);
            acc[0][1] = ffma2(a01.x, w01.y, acc[0][1]);
            acc[0][2] = ffma2(a01.x, w23.x, acc[0][2]);
            acc[0][3] = ffma2(a01.x, w23.y, acc[0][3]);
            acc[1][0] = ffma2(a01.y, w01.x, acc[1][0]);
            acc[1][1] = ffma2(a01.y, w01.y, acc[1][1]);
            acc[1][2] = ffma2(a01.y, w23.x, acc[1][2]);
            acc[1][3] = ffma2(a01.y, w23.y, acc[1][3]);
            acc[2][0] = ffma2(a23.x, w01.x, acc[2][0]);
            acc[2][1] = ffma2(a23.x, w01.y, acc[2][1]);
            acc[2][2] = ffma2(a23.x, w23.x, acc[2][2]);
            acc[2][3] = ffma2(a23.x, w23.y, acc[2][3]);
            acc[3][0] = ffma2(a23.y, w01.x, acc[3][0]);
            acc[3][1] = ffma2(a23.y, w01.y, acc[3][1]);
            acc[3][2] = ffma2(a23.y, w23.x, acc[3][2]);
            acc[3][3] = ffma2(a23.y, w23.y, acc[3][3]);
        }
        if (c + 1 < K1_NC) {
            const int nxt = (c + 1) & 1;
            sA[nxt][fg * 4 + 0][fb] = make_float2(pa.x, pa.x);
            sA[nxt][fg * 4 + 1][fb] = make_float2(pa.y, pa.y);
            sA[nxt][fg * 4 + 2][fb] = make_float2(pa.z, pa.z);
            sA[nxt][fg * 4 + 3][fb] = make_float2(pa.w, pa.w);
            *(float4*)&sB[nxt][wk][wg * 8]     = pw0;
            *(float4*)&sB[nxt][wk][wg * 8 + 4] = pw1;
            __syncthreads();
        }
    }

#pragma unroll
    for (int p = 0; p < 4; p++) {
        const int b = byy * 4 + p;
        *(ulonglong2*)&g_px[ks][b][s0 + sx * 4]      = make_ulonglong2(acc[p][0], acc[p][1]);
        *(ulonglong2*)&g_px[ks][b][s0 + 64 + sx * 4] = make_ulonglong2(acc[p][2], acc[p][3]);
    }
}

// ============ KB: argmax partial blocks + update GEMM (spin for gather) =====
__global__ __launch_bounds__(128) void kb(
    int t, const float* __restrict__ s2a, const float* __restrict__ Wres,
    const float* __restrict__ bx)
{
    const int tid = threadIdx.x;

    if (blockIdx.x < NAMB) {
        // ------- argmax partial block: one (b, 512-wide s segment) -------
        __shared__ ull red[4];
        const int b = blockIdx.x >> 3;
        const int s = (blockIdx.x & 7) * 512 + tid * 4;
        float4 v = *(const float4*)&bx[s];
#pragma unroll
        for (int ks = 0; ks < K1_KSPLIT; ks++) {
            float4 p = *(const float4*)&g_px[ks][b][s];
            v.x += p.x; v.y += p.y; v.z += p.z; v.w += p.w;
        }
        float best = v.x; int bi = s;
        if (v.y > best) { best = v.y; bi = s + 1; }
        if (v.z > best) { best = v.z; bi = s + 2; }
        if (v.w > best) { best = v.w; bi = s + 3; }
        ull key = ((ull)f2ord(best) << 32) | (ull)(0xFFFFFFFFu - (unsigned)bi);
#pragma unroll
        for (int off = 16; off; off >>= 1) {
            ull o = __shfl_down_sync(0xFFFFFFFFu, key, off);
            if (o > key) key = o;
        }
        if ((tid & 31) == 0) red[tid >> 5] = key;
        __syncthreads();
        if (tid == 0) {
            ull k = red[0];
#pragma unroll
            for (int w = 1; w < 4; w++) if (red[w] > k) k = red[w];
            atomicMax(&g_amax[b], k);   // max: order-independent, deterministic
            __threadfence();
            atomicAdd(&g_arrived, 1);
        }
        return;
    }

    // ------- GEMM block -------
    if (g_done_flag[t]) return;   // frozen: keep pu (h stays fixed)

    __shared__ __align__(16) float2 sA[2][K2_KC][B];
    __shared__ __align__(16) float  sB[2][K2_KC][K2_JB];
    __shared__ int sPtr[B];

    const int q = blockIdx.x - NAMB;
    const int ks = q >> 4, jb = q & 15;
    const int k0 = ks * K2_KR, j0 = jb * K2_JB;
    const bool gat = (k0 >= H);
    const float* __restrict__ hn = g_hn;

    if (gat) {
        if (tid == 0) {
            while (atomicAdd(&g_arrived, 0) < NAMB) __nanosleep(128);
        }
        __syncthreads();
        __threadfence();
        if (tid < B) {
            ull k = g_amax[tid];
            int p = (int)(0xFFFFFFFFu - (unsigned)(k & 0xFFFFFFFFull));
            sPtr[tid] = (p < S) ? p : (S - 1);
        }
        __syncthreads();
    }

    const int fb = tid >> 1, fg = tid & 1;   // A fill
    const int wk = tid >> 3, wg = tid & 7;   // B fill
    const int byy = tid >> 3, jx = tid & 7;

    ull acc[4][4];
#pragma unroll
    for (int p = 0; p < 4; p++)
#pragma unroll
        for (int q2 = 0; q2 < 4; q2++) acc[p][q2] = 0ull;

    const float* arow0 = gat ? s2a + ((size_t)fb * S + sPtr[fb]) * H + (k0 - H)
                             : hn + fb * H + k0;

    {   // fill chunk 0
        float4 a0 = *(const float4*)(arow0 + fg * 8);
        float4 a1 = *(const float4*)(arow0 + fg * 8 + 4);
        sA[0][fg * 8 + 0][fb] = make_float2(a0.x, a0.x);
        sA[0][fg * 8 + 1][fb] = make_float2(a0.y, a0.y);
        sA[0][fg * 8 + 2][fb] = make_float2(a0.z, a0.z);
        sA[0][fg * 8 + 3][fb] = make_float2(a0.w, a0.w);
        sA[0][fg * 8 + 4][fb] = make_float2(a1.x, a1.x);
        sA[0][fg * 8 + 5][fb] = make_float2(a1.y, a1.y);
        sA[0][fg * 8 + 6][fb] = make_float2(a1.z, a1.z);
        sA[0][fg * 8 + 7][fb] = make_float2(a1.w, a1.w);
        const float* wr = Wres + (size_t)(k0 + wk) * H + j0 + wg * 8;
        *(float4*)&sB[0][wk][wg * 8]     = *(const float4*)wr;
        *(float4*)&sB[0][wk][wg * 8 + 4] = *(const float4*)(wr + 4);
    }
    __syncthreads();

    for (int c = 0; c < K2_NC; c++) {
        const int cur = c & 1;
        float4 pa0, pa1, pw0, pw1;
        if (c + 1 < K2_NC) {
            const int kof = (c + 1) * K2_KC;
            pa0 = *(const float4*)(arow0 + kof + fg * 8);
            pa1 = *(const float4*)(arow0 + kof + fg * 8 + 4);
            const float* wr = Wres + (size_t)(k0 + kof + wk) * H + j0 + wg * 8;
            pw0 = *(const float4*)wr;
            pw1 = *(const float4*)(wr + 4);
        }
#pragma unroll
        for (int kk = 0; kk < K2_KC; kk++) {
            ulonglong2 a01 = *(const ulonglong2*)&sA[cur][kk][byy * 4];
            ulonglong2 a23 = *(const ulonglong2*)&sA[cur][kk][byy * 4 + 2];
            ulonglong2 w01 = *(const ulonglong2*)&sB[cur][kk][jx * 4];
            ulonglong2 w23 = *(const ulonglong2*)&sB[cur][kk][32 + jx * 4];
            acc[0][0] = ffma2(a01.x, w01.x, acc[0][0]);
            acc[0][1] = ffma2(a01.x, w01.y, acc[0][1]);
            acc[0][2] = ffma2(a01.x, w23.x, acc[0][2]);
            acc[0][3] = ffma2(a01.x, w23.y, acc[0][3]);
            acc[1][0] = ffma2(a01.y, w01.x, acc[1][0]);
            acc[1][1] = ffma2(a01.y, w01.y, acc[1][1]);
            acc[1][2] = ffma2(a01.y, w23.x, acc[1][2]);
            acc[1][3] = ffma2(a01.y, w23.y, acc[1][3]);
            acc[2][0] = ffma2(a23.x, w01.x, acc[2][0]);
            acc[2][1] = ffma2(a23.x, w01.y, acc[2][1]);
            acc[2][2] = ffma2(a23.x, w23.x, acc[2][2]);
            acc[2][3] = ffma2(a23.x, w23.y, acc[2][3]);
            acc[3][0] = ffma2(a23.y, w01.x, acc[3][0]);
            acc[3][1] = ffma2(a23.y, w01.y, acc[3][1]);
            acc[3][2] = ffma2(a23.y, w23.x, acc[3][2]);
            acc[3][3] = ffma2(a23.y, w23.y, acc[3][3]);
        }
        if (c + 1 < K2_NC) {
            const int nxt = (c + 1) & 1;
            sA[nxt][fg * 8 + 0][fb] = make_float2(pa0.x, pa0.x);
            sA[nxt][fg * 8 + 1][fb] = make_float2(pa0.y, pa0.y);
            sA[nxt][fg * 8 + 2][fb] = make_float2(pa0.z, pa0.z);
            sA[nxt][fg * 8 + 3][fb] = make_float2(pa0.w, pa0.w);
            sA[nxt][fg * 8 + 4][fb] = make_float2(pa1.x, pa1.x);
            sA[nxt][fg * 8 + 5][fb] = make_float2(pa1.y, pa1.y);
            sA[nxt][fg * 8 + 6][fb] = make_float2(pa1.z, pa1.z);
            sA[nxt][fg * 8 + 7][fb] = make_float2(pa1.w, pa1.w);
            *(float4*)&sB[nxt][wk][wg * 8]     = pw0;
            *(float4*)&sB[nxt][wk][wg * 8 + 4] = pw1;
            __syncthreads();
        }
    }

#pragma unroll
    for (int p = 0; p < 4; p++) {
        const int b = byy * 4 + p;
        *(ulonglong2*)&g_pu[ks][b][j0 + jx * 4]      = make_ulonglong2(acc[p][0], acc[p][1]);
        *(ulonglong2*)&g_pu[ks][b][j0 + 32 + jx * 4] = make_ulonglong2(acc[p][2], acc[p][3]);
    }
}

// ============ KO: final combine -> out =====================================
__global__ __launch_bounds__(256) void ko(const float* __restrict__ bres,
                                          float* __restrict__ out)
{
    const int b = blockIdx.x, tid = threadIdx.x;
    const int j = tid * 4;
    float4 a = make_float4(0.f, 0.f, 0.f, 0.f);
#pragma unroll
    for (int ks = 0; ks < K2_KSPLIT; ks++) {
        float4 p = *(const float4*)&g_pu[ks][b][j];
        a.x += p.x; a.y += p.y; a.z += p.z; a.w += p.w;
    }
    float4 bb = *(const float4*)&bres[j];
    *(float4*)&out[b * H + j] = make_float4(a.x + bb.x, a.y + bb.y,
                                            a.z + bb.z, a.w + bb.w);
}

extern "C" void kernel_launch(void* const* d_in, const int* in_sizes, int n_in,
                              void* d_out, int out_size) {
    const float* s2a   = (const float*)d_in[0];
    const float* Wres  = (const float*)d_in[1];
    const float* bres  = (const float*)d_in[2];
    const float* Wop   = (const float*)d_in[3];
    const float* bop   = (const float*)d_in[4];
    const float* Wx    = (const float*)d_in[5];
    const float* bx    = (const float*)d_in[6];
    const float* noise = (const float*)d_in[7];
    float* out = (float*)d_out;

    for (int t = 0; t < TSTEPS; t++) {
        kf<<<B * 8 + 1, 128>>>(t, bres, noise);
        ka<<<KA_GRID, 256>>>(t, Wx, Wop, bop);
        kb<<<KB_GRID, 128>>>(t, s2a, Wres, bx);
    }
    ko<<<B, 256>>>(bres, out);
}